// round 11
// baseline (speedup 1.0000x reference)
#include <cuda_runtime.h>
#include <cuda_bf16.h>
#include <cstdint>

#define B_ 32
#define L_ 512
#define D_ 512
#define S_ 8
#define BL_ (B_ * L_)

// ---------------- static device scratch ----------------
__device__ __nv_bfloat16 g_A1h[(size_t)BL_ * D_];
__device__ __nv_bfloat16 g_A1l[(size_t)BL_ * D_];
__device__ __nv_bfloat16 g_A2h[(size_t)BL_ * D_];
__device__ __nv_bfloat16 g_A2l[(size_t)BL_ * D_];
__device__ __nv_bfloat16 g_Mth[(size_t)S_ * D_ * D_];  // Mr^T [k][e][d]
__device__ __nv_bfloat16 g_Mtl[(size_t)S_ * D_ * D_];
__device__ __nv_bfloat16 g_Ph[(size_t)B_ * S_ * L_ * D_];  // P [b,k,i,e]
__device__ __nv_bfloat16 g_Pl[(size_t)B_ * S_ * L_ * D_];
// factored sigmoid tables: exp(-g1), exp(-(g2+Bg)), exp(-s1), exp(-s2)
__device__ float g_EG1[BL_ * S_], g_EG2[BL_ * S_], g_ES1[BL_ * S_], g_ES2[BL_ * S_];

// ---------------- helpers ----------------
__device__ __forceinline__ uint32_t smem_u32(const void* p) {
    return (uint32_t)__cvta_generic_to_shared(p);
}
__device__ __forceinline__ void ldm_x4(uint32_t* r, uint32_t a) {
    asm volatile("ldmatrix.sync.aligned.m8n8.x4.shared.b16 {%0,%1,%2,%3}, [%4];"
                 : "=r"(r[0]), "=r"(r[1]), "=r"(r[2]), "=r"(r[3]) : "r"(a));
}
__device__ __forceinline__ void ldm_x2(uint32_t* r, uint32_t a) {
    asm volatile("ldmatrix.sync.aligned.m8n8.x2.shared.b16 {%0,%1}, [%2];"
                 : "=r"(r[0]), "=r"(r[1]) : "r"(a));
}
__device__ __forceinline__ void mma_bf16(float* d, const uint32_t* a, const uint32_t* b) {
    asm volatile(
        "mma.sync.aligned.m16n8k16.row.col.f32.bf16.bf16.f32 "
        "{%0,%1,%2,%3},{%4,%5,%6,%7},{%8,%9},{%0,%1,%2,%3};"
        : "+f"(d[0]), "+f"(d[1]), "+f"(d[2]), "+f"(d[3])
        : "r"(a[0]), "r"(a[1]), "r"(a[2]), "r"(a[3]), "r"(b[0]), "r"(b[1]));
}
__device__ __forceinline__ void cp16(uint32_t dst, const void* src) {
    asm volatile("cp.async.cg.shared.global [%0], [%1], 16;" ::"r"(dst), "l"(src));
}
#define CP_COMMIT() asm volatile("cp.async.commit_group;" ::: "memory")
#define CP_WAIT1() asm volatile("cp.async.wait_group 1;" ::: "memory")
#define CP_WAIT0() asm volatile("cp.async.wait_group 0;" ::: "memory")

// Newton reciprocal (no MUFU): a >= 1 here.
__device__ __forceinline__ float rcp_nr(float a) {
    float r = __uint_as_float(0x7EF311C3u - __float_as_uint(a));
    r = r * fmaf(-a, r, 2.0f);
    r = r * fmaf(-a, r, 2.0f);
    r = r * fmaf(-a, r, 2.0f);
    return r;
}
__device__ __forceinline__ float nexp(float x) {  // exp(-clamp(x, +/-40))
    x = fminf(fmaxf(x, -40.f), 40.f);
    return expf(-x);
}
__device__ __forceinline__ uint32_t pack_bf2(float f0, float f1,
                                             uint32_t& lopack) {
    __nv_bfloat16 h0 = __float2bfloat16(f0), h1 = __float2bfloat16(f1);
    __nv_bfloat16 l0 = __float2bfloat16(f0 - __bfloat162float(h0));
    __nv_bfloat16 l1 = __float2bfloat16(f1 - __bfloat162float(h1));
    lopack = (uint32_t)__bfloat16_as_ushort(l0) |
             ((uint32_t)__bfloat16_as_ushort(l1) << 16);
    return (uint32_t)__bfloat16_as_ushort(h0) |
           ((uint32_t)__bfloat16_as_ushort(h1) << 16);
}

// stage layout (both GEMM kernels): Ah@0 (128x32, pitch 80 -> 10240),
// Al@10240, Bh@20480 (64x32 pitch 80 -> 5120), Bl@25600. stage = 30720.
#define STG 30720u

// ---------------------------------------------------------------------------
// Kernel 1: projections -> exp tables, plus fp32->bf16(hi,lo) of arg1/arg2.
// ---------------------------------------------------------------------------
__global__ __launch_bounds__(256) void proj_convert(
    const float* __restrict__ arg1, const float* __restrict__ arg2,
    const float* __restrict__ Wg, const float* __restrict__ V,
    const float* __restrict__ Bg) {
    extern __shared__ float wsm[];  // [0:8192) Wg^T [s][1024], [8192:16384) V^T
    for (int t = threadIdx.x; t < 8192; t += 256) {
        int d = t >> 3, s = t & 7;
        wsm[s * 1024 + d] = Wg[t];
        wsm[8192 + s * 1024 + d] = V[t];
    }
    __syncthreads();
    int w = threadIdx.x >> 5, lane = threadIdx.x & 31;
    int r = blockIdx.x * 8 + w;
    const float* a1 = arg1 + (size_t)r * D_;
    const float* a2 = arg2 + (size_t)r * D_;
    float aG1[8] = {}, aG2[8] = {}, aS1[8] = {}, aS2[8] = {};
#pragma unroll
    for (int t = 0; t < 16; t++) {
        int d = lane + t * 32;
        float v1 = a1[d], v2 = a2[d];
        __nv_bfloat16 h1 = __float2bfloat16(v1);
        g_A1h[(size_t)r * D_ + d] = h1;
        g_A1l[(size_t)r * D_ + d] = __float2bfloat16(v1 - __bfloat162float(h1));
        __nv_bfloat16 h2 = __float2bfloat16(v2);
        g_A2h[(size_t)r * D_ + d] = h2;
        g_A2l[(size_t)r * D_ + d] = __float2bfloat16(v2 - __bfloat162float(h2));
#pragma unroll
        for (int s = 0; s < 8; s++) {
            aG1[s] += v1 * wsm[s * 1024 + d];
            aG2[s] += v2 * wsm[s * 1024 + 512 + d];
            aS1[s] += v1 * wsm[8192 + s * 1024 + d];
            aS2[s] += v2 * wsm[8192 + s * 1024 + 512 + d];
        }
    }
#pragma unroll
    for (int m = 16; m; m >>= 1) {
#pragma unroll
        for (int s = 0; s < 8; s++) {
            aG1[s] += __shfl_xor_sync(0xffffffffu, aG1[s], m);
            aG2[s] += __shfl_xor_sync(0xffffffffu, aG2[s], m);
            aS1[s] += __shfl_xor_sync(0xffffffffu, aS1[s], m);
            aS2[s] += __shfl_xor_sync(0xffffffffu, aS2[s], m);
        }
    }
    if (lane == 0) {
#pragma unroll
        for (int s = 0; s < 8; s++) {
            g_EG1[r * 8 + s] = nexp(aG1[s]);
            g_EG2[r * 8 + s] = nexp(aG2[s] + Bg[s]);
            g_ES1[r * 8 + s] = nexp(aS1[s]);
            g_ES2[r * 8 + s] = nexp(aS2[s]);
        }
    }
}

// ---------------------------------------------------------------------------
// Kernel 2: Mr [k,d,e] -> transposed bf16 split Mt [k,e,d].
// ---------------------------------------------------------------------------
__global__ void mr_transpose(const float* __restrict__ Mr) {
    __shared__ float tile[32][33];
    int k = blockIdx.z;
    int d0 = blockIdx.y * 32, e0 = blockIdx.x * 32;
    const float* src = Mr + (size_t)k * D_ * D_;
    for (int rr = threadIdx.y; rr < 32; rr += 8)
        tile[rr][threadIdx.x] = src[(size_t)(d0 + rr) * D_ + e0 + threadIdx.x];
    __syncthreads();
    __nv_bfloat16* dh = g_Mth + (size_t)k * D_ * D_;
    __nv_bfloat16* dl = g_Mtl + (size_t)k * D_ * D_;
    for (int rr = threadIdx.y; rr < 32; rr += 8) {
        float v = tile[threadIdx.x][rr];
        __nv_bfloat16 h = __float2bfloat16(v);
        dh[(size_t)(e0 + rr) * D_ + d0 + threadIdx.x] = h;
        dl[(size_t)(e0 + rr) * D_ + d0 + threadIdx.x] =
            __float2bfloat16(v - __bfloat162float(h));
    }
}

// ---------------------------------------------------------------------------
// Kernel 3: P = arg1 @ Mr^T (split-bf16, 3 passes). CTA 128(M)x64(N), BK=32.
// 8 warps as 4M x 2N -> acc 32 regs, 2 CTAs/SM. grid = (8, 128, 8).
// ---------------------------------------------------------------------------
__global__ __launch_bounds__(256, 2) void pmul_mma() {
    const int k = blockIdx.z, mB = blockIdx.y, nB = blockIdx.x;
    extern __shared__ char sm[];
    const uint32_t sb = smem_u32(sm);
    const int tid = threadIdx.x, wid = tid >> 5, lane = tid & 31;
    const int warpM = wid >> 1, warpN = wid & 1;

    const __nv_bfloat16* pAh = g_A1h + (size_t)mB * 128 * D_;
    const __nv_bfloat16* pAl = g_A1l + (size_t)mB * 128 * D_;
    const __nv_bfloat16* pBh = g_Mth + ((size_t)k * D_ + nB * 64) * D_;
    const __nv_bfloat16* pBl = g_Mtl + ((size_t)k * D_ + nB * 64) * D_;

    auto load_chunk = [&](int c, int buf) {
        uint32_t dstb = sb + (uint32_t)buf * STG;
#pragma unroll
        for (int rr = 0; rr < 2; rr++) {
            int op = tid + rr * 256;
            int row = op >> 2, seg = op & 3;
            uint32_t off = (uint32_t)(row * 80 + seg * 16);
            size_t gi = (size_t)row * D_ + c * 32 + seg * 8;
            cp16(dstb + off, pAh + gi);
            cp16(dstb + 10240u + off, pAl + gi);
        }
        {
            int row = tid >> 2, seg = tid & 3;
            uint32_t off = (uint32_t)(row * 80 + seg * 16);
            size_t gi = (size_t)row * D_ + c * 32 + seg * 8;
            cp16(dstb + 20480u + off, pBh + gi);
            cp16(dstb + 25600u + off, pBl + gi);
        }
    };

    float acc[2][4][4];
#pragma unroll
    for (int mt = 0; mt < 2; mt++)
#pragma unroll
        for (int nt = 0; nt < 4; nt++)
#pragma unroll
            for (int q = 0; q < 4; q++) acc[mt][nt][q] = 0.f;

    load_chunk(0, 0);
    CP_COMMIT();
    const int lm = lane & 15, lk = lane >> 4;
    const int bn = lane & 7, bk2 = (lane >> 3) & 1;

    for (int c = 0; c < 16; c++) {
        int buf = c & 1;
        if (c + 1 < 16) { load_chunk(c + 1, buf ^ 1); CP_COMMIT(); CP_WAIT1(); }
        else CP_WAIT0();
        __syncthreads();
        uint32_t sbuf = sb + (uint32_t)buf * STG;
#pragma unroll
        for (int ks = 0; ks < 2; ks++) {
            uint32_t ah[2][4], al[2][4], bh[4][2], bl[4][2];
#pragma unroll
            for (int mt = 0; mt < 2; mt++) {
                uint32_t a = sbuf + (uint32_t)((warpM * 32 + mt * 16 + lm) * 80 +
                                               (ks * 16 + lk * 8) * 2);
                ldm_x4(ah[mt], a);
                ldm_x4(al[mt], a + 10240u);
            }
#pragma unroll
            for (int nt = 0; nt < 4; nt++) {
                uint32_t a = sbuf + 20480u +
                             (uint32_t)((warpN * 32 + nt * 8 + bn) * 80 +
                                        (ks * 16 + bk2 * 8) * 2);
                ldm_x2(bh[nt], a);
                ldm_x2(bl[nt], a + 5120u);
            }
#pragma unroll
            for (int mt = 0; mt < 2; mt++)
#pragma unroll
                for (int nt = 0; nt < 4; nt++) {
                    mma_bf16(acc[mt][nt], ah[mt], bh[nt]);
                    mma_bf16(acc[mt][nt], ah[mt], bl[nt]);
                    mma_bf16(acc[mt][nt], al[mt], bh[nt]);
                }
        }
        __syncthreads();
    }

    // epilogue: split to bf16 hi/lo and store P
    const int rowg0 = mB * 128 + warpM * 32;
#pragma unroll
    for (int mt = 0; mt < 2; mt++) {
#pragma unroll
        for (int half = 0; half < 2; half++) {
            int rowg = rowg0 + mt * 16 + (lane >> 2) + half * 8;
            int bb = rowg >> 9, ii = rowg & 511;
            size_t base = ((size_t)(bb * S_ + k) * L_ + ii) * D_ + nB * 64;
#pragma unroll
            for (int nt = 0; nt < 4; nt++) {
                int colg = warpN * 32 + nt * 8 + (lane & 3) * 2;
                uint32_t wl;
                uint32_t wh = pack_bf2(acc[mt][nt][half * 2],
                                       acc[mt][nt][half * 2 + 1], wl);
                *(uint32_t*)(g_Ph + base + colg) = wh;
                *(uint32_t*)(g_Pl + base + colg) = wl;
            }
        }
    }
}

// ---------------------------------------------------------------------------
// Kernel 4: per (b, i-tile 128, j-tile 64): loop k, bi = P @ arg2^T (split-bf16)
// + fused factored-sigmoid gating, final sigmoid. 8 warps as 4M x 2N.
// smem: 2 stages x 30720 + exp tables @61440. grid = (8, 4, 32). 2 CTAs/SM.
// ---------------------------------------------------------------------------
__global__ __launch_bounds__(256, 2) void score_mma(
    const float* __restrict__ U, const float* __restrict__ bvec,
    float* __restrict__ out) {
    const int b = blockIdx.z;
    const int i0 = blockIdx.y * 128;
    const int j0 = blockIdx.x * 64;
    extern __shared__ char sm[];
    const uint32_t sb = smem_u32(sm);
    float* EG1t = (float*)(sm + 61440);  // [128][9]
    float* ES1t = (float*)(sm + 66048);  // [128][9]
    float* EG2t = (float*)(sm + 70656);  // [8][64]
    float* ES2t = (float*)(sm + 72704);  // [8][64]
    const int tid = threadIdx.x, wid = tid >> 5, lane = tid & 31;
    const int warpM = wid >> 1, warpN = wid & 1;

    for (int t = tid; t < 1024; t += 256) {
        int r = t >> 3, s = t & 7;
        EG1t[r * 9 + s] = g_EG1[(size_t)(b * L_ + i0 + r) * 8 + s];
        ES1t[r * 9 + s] = g_ES1[(size_t)(b * L_ + i0 + r) * 8 + s];
    }
    for (int t = tid; t < 512; t += 256) {
        int kk = t >> 6, j = t & 63;
        EG2t[kk * 64 + j] = g_EG2[(size_t)(b * L_ + j0 + j) * 8 + kk];
        ES2t[kk * 64 + j] = g_ES2[(size_t)(b * L_ + j0 + j) * 8 + kk];
    }

    float Ur[8];
#pragma unroll
    for (int s = 0; s < 8; s++) Ur[s] = __ldg(U + s);
    float c0 = 0.f;
#pragma unroll
    for (int s = 0; s < 8; s++) c0 += Ur[s] * __ldg(bvec + s);

    const __nv_bfloat16* pBh = g_A2h + (size_t)(b * L_ + j0) * D_;
    const __nv_bfloat16* pBl = g_A2l + (size_t)(b * L_ + j0) * D_;

    auto load_chunk = [&](int cc, int buf) {
        int k = cc >> 4, c = cc & 15;
        const __nv_bfloat16* pAh = g_Ph + ((size_t)(b * S_ + k) * L_ + i0) * D_;
        const __nv_bfloat16* pAl = g_Pl + ((size_t)(b * S_ + k) * L_ + i0) * D_;
        uint32_t dstb = sb + (uint32_t)buf * STG;
#pragma unroll
        for (int rr = 0; rr < 2; rr++) {
            int op = tid + rr * 256;
            int row = op >> 2, seg = op & 3;
            uint32_t off = (uint32_t)(row * 80 + seg * 16);
            size_t gi = (size_t)row * D_ + c * 32 + seg * 8;
            cp16(dstb + off, pAh + gi);
            cp16(dstb + 10240u + off, pAl + gi);
        }
        {
            int row = tid >> 2, seg = tid & 3;
            uint32_t off = (uint32_t)(row * 80 + seg * 16);
            size_t gi = (size_t)row * D_ + c * 32 + seg * 8;
            cp16(dstb + 20480u + off, pBh + gi);
            cp16(dstb + 25600u + off, pBl + gi);
        }
    };

    float acc[2][4][4], part[2][4][4];
#pragma unroll
    for (int mt = 0; mt < 2; mt++)
#pragma unroll
        for (int nt = 0; nt < 4; nt++)
#pragma unroll
            for (int q = 0; q < 4; q++) part[mt][nt][q] = 0.f;

    load_chunk(0, 0);
    CP_COMMIT();
    const int lm = lane & 15, lk = lane >> 4;
    const int bn = lane & 7, bk2 = (lane >> 3) & 1;

    for (int cc = 0; cc < 128; cc++) {
        int k = cc >> 4, c = cc & 15, buf = cc & 1;
        if (cc + 1 < 128) { load_chunk(cc + 1, buf ^ 1); CP_COMMIT(); CP_WAIT1(); }
        else CP_WAIT0();
        __syncthreads();
        if (c == 0) {
#pragma unroll
            for (int mt = 0; mt < 2; mt++)
#pragma unroll
                for (int nt = 0; nt < 4; nt++)
#pragma unroll
                    for (int q = 0; q < 4; q++) acc[mt][nt][q] = 0.f;
        }
        uint32_t sbuf = sb + (uint32_t)buf * STG;
#pragma unroll
        for (int ks = 0; ks < 2; ks++) {
            uint32_t ah[2][4], al[2][4], bh[4][2], bl[4][2];
#pragma unroll
            for (int mt = 0; mt < 2; mt++) {
                uint32_t a = sbuf + (uint32_t)((warpM * 32 + mt * 16 + lm) * 80 +
                                               (ks * 16 + lk * 8) * 2);
                ldm_x4(ah[mt], a);
                ldm_x4(al[mt], a + 10240u);
            }
#pragma unroll
            for (int nt = 0; nt < 4; nt++) {
                uint32_t a = sbuf + 20480u +
                             (uint32_t)((warpN * 32 + nt * 8 + bn) * 80 +
                                        (ks * 16 + bk2 * 8) * 2);
                ldm_x2(bh[nt], a);
                ldm_x2(bl[nt], a + 5120u);
            }
#pragma unroll
            for (int mt = 0; mt < 2; mt++)
#pragma unroll
                for (int nt = 0; nt < 4; nt++) {
                    mma_bf16(acc[mt][nt], ah[mt], bh[nt]);
                    mma_bf16(acc[mt][nt], ah[mt], bl[nt]);
                    mma_bf16(acc[mt][nt], al[mt], bh[nt]);
                }
        }
        if (c == 15) {
            float Uk = Ur[k];
#pragma unroll
            for (int mt = 0; mt < 2; mt++) {
                int r0 = warpM * 32 + mt * 16 + (lane >> 2);
                float eg1a = EG1t[r0 * 9 + k], es1a = ES1t[r0 * 9 + k];
                float eg1b = EG1t[(r0 + 8) * 9 + k], es1b = ES1t[(r0 + 8) * 9 + k];
#pragma unroll
                for (int nt = 0; nt < 4; nt++) {
                    int jj = warpN * 32 + nt * 8 + (lane & 3) * 2;
                    float eg2x = EG2t[k * 64 + jj], eg2y = EG2t[k * 64 + jj + 1];
                    float es2x = ES2t[k * 64 + jj], es2y = ES2t[k * 64 + jj + 1];
                    float g, s;
                    g = rcp_nr(fmaf(eg1a, eg2x, 1.f));
                    s = rcp_nr(fmaf(es1a, es2x, 1.f));
                    part[mt][nt][0] =
                        fmaf(Uk, fmaf(g, acc[mt][nt][0] - s, s), part[mt][nt][0]);
                    g = rcp_nr(fmaf(eg1a, eg2y, 1.f));
                    s = rcp_nr(fmaf(es1a, es2y, 1.f));
                    part[mt][nt][1] =
                        fmaf(Uk, fmaf(g, acc[mt][nt][1] - s, s), part[mt][nt][1]);
                    g = rcp_nr(fmaf(eg1b, eg2x, 1.f));
                    s = rcp_nr(fmaf(es1b, es2x, 1.f));
                    part[mt][nt][2] =
                        fmaf(Uk, fmaf(g, acc[mt][nt][2] - s, s), part[mt][nt][2]);
                    g = rcp_nr(fmaf(eg1b, eg2y, 1.f));
                    s = rcp_nr(fmaf(es1b, es2y, 1.f));
                    part[mt][nt][3] =
                        fmaf(Uk, fmaf(g, acc[mt][nt][3] - s, s), part[mt][nt][3]);
                }
            }
        }
        __syncthreads();
    }

    // final sigmoid + store
#pragma unroll
    for (int mt = 0; mt < 2; mt++) {
        int ibase = i0 + warpM * 32 + mt * 16 + (lane >> 2);
#pragma unroll
        for (int half = 0; half < 2; half++) {
            float* orow = out + ((size_t)b * L_ + ibase + half * 8) * L_ + j0;
#pragma unroll
            for (int nt = 0; nt < 4; nt++) {
                int jj = warpN * 32 + nt * 8 + (lane & 3) * 2;
                float z0 = part[mt][nt][half * 2 + 0] + c0;
                float z1 = part[mt][nt][half * 2 + 1] + c0;
                float2 v;
                v.x = rcp_nr(1.f + __expf(-z0));
                v.y = rcp_nr(1.f + __expf(-z1));
                *(float2*)(orow + jj) = v;
            }
        }
    }
}

// ---------------------------------------------------------------------------
extern "C" void kernel_launch(void* const* d_in, const int* in_sizes, int n_in,
                              void* d_out, int out_size) {
    const float* arg1 = (const float*)d_in[0];
    const float* arg2 = (const float*)d_in[1];
    const float* Wg   = (const float*)d_in[2];
    const float* Bg   = (const float*)d_in[3];
    const float* Mr   = (const float*)d_in[4];
    const float* V    = (const float*)d_in[5];
    const float* bvec = (const float*)d_in[6];
    const float* U    = (const float*)d_in[7];
    float* out = (float*)d_out;
    (void)in_sizes; (void)n_in; (void)out_size;

    const int SMEM_PROJ = 65536;
    const int SMEM_B = 61440;
    const int SMEM_C = 74752;
    cudaFuncSetAttribute(proj_convert, cudaFuncAttributeMaxDynamicSharedMemorySize, SMEM_PROJ);
    cudaFuncSetAttribute(pmul_mma, cudaFuncAttributeMaxDynamicSharedMemorySize, SMEM_B);
    cudaFuncSetAttribute(score_mma, cudaFuncAttributeMaxDynamicSharedMemorySize, SMEM_C);

    proj_convert<<<BL_ / 8, 256, SMEM_PROJ>>>(arg1, arg2, Wg, V, Bg);
    mr_transpose<<<dim3(16, 16, 8), dim3(32, 8)>>>(Mr);
    pmul_mma<<<dim3(8, 128, 8), 256, SMEM_B>>>();
    score_mma<<<dim3(8, 4, 32), 256, SMEM_C>>>(U, bvec, out);
}

// round 13
// speedup vs baseline: 1.4951x; 1.4951x over previous
#include <cuda_runtime.h>
#include <cuda_bf16.h>
#include <cstdint>

#define B_ 32
#define L_ 512
#define D_ 512
#define S_ 8
#define BL_ (B_ * L_)

// ---------------- static device scratch ----------------
__device__ __nv_bfloat16 g_A1h[(size_t)BL_ * D_];
__device__ __nv_bfloat16 g_A1l[(size_t)BL_ * D_];
__device__ __nv_bfloat16 g_A2h[(size_t)BL_ * D_];
__device__ __nv_bfloat16 g_A2l[(size_t)BL_ * D_];
__device__ __nv_bfloat16 g_Mth[(size_t)S_ * D_ * D_];  // Mr^T [k][e][d]
__device__ __nv_bfloat16 g_Mtl[(size_t)S_ * D_ * D_];
__device__ __nv_bfloat16 g_Ph[(size_t)B_ * S_ * L_ * D_];  // P [b,k,i,e]
__device__ __nv_bfloat16 g_Pl[(size_t)B_ * S_ * L_ * D_];
// factored sigmoid tables: exp(-g1), exp(-(g2+Bg)), exp(-s1), exp(-s2)
__device__ float g_EG1[BL_ * S_], g_EG2[BL_ * S_], g_ES1[BL_ * S_], g_ES2[BL_ * S_];

// ---------------- helpers ----------------
__device__ __forceinline__ uint32_t smem_u32(const void* p) {
    return (uint32_t)__cvta_generic_to_shared(p);
}
__device__ __forceinline__ void ldm_x4(uint32_t* r, uint32_t a) {
    asm volatile("ldmatrix.sync.aligned.m8n8.x4.shared.b16 {%0,%1,%2,%3}, [%4];"
                 : "=r"(r[0]), "=r"(r[1]), "=r"(r[2]), "=r"(r[3]) : "r"(a));
}
__device__ __forceinline__ void ldm_x2(uint32_t* r, uint32_t a) {
    asm volatile("ldmatrix.sync.aligned.m8n8.x2.shared.b16 {%0,%1}, [%2];"
                 : "=r"(r[0]), "=r"(r[1]) : "r"(a));
}
__device__ __forceinline__ void mma_bf16(float* d, const uint32_t* a, const uint32_t* b) {
    asm volatile(
        "mma.sync.aligned.m16n8k16.row.col.f32.bf16.bf16.f32 "
        "{%0,%1,%2,%3},{%4,%5,%6,%7},{%8,%9},{%0,%1,%2,%3};"
        : "+f"(d[0]), "+f"(d[1]), "+f"(d[2]), "+f"(d[3])
        : "r"(a[0]), "r"(a[1]), "r"(a[2]), "r"(a[3]), "r"(b[0]), "r"(b[1]));
}
__device__ __forceinline__ void cp16(uint32_t dst, const void* src) {
    asm volatile("cp.async.cg.shared.global [%0], [%1], 16;" ::"r"(dst), "l"(src));
}
#define CP_COMMIT() asm volatile("cp.async.commit_group;" ::: "memory")
#define CP_WAIT2() asm volatile("cp.async.wait_group 2;" ::: "memory")
#define CP_WAIT1() asm volatile("cp.async.wait_group 1;" ::: "memory")
#define CP_WAIT0() asm volatile("cp.async.wait_group 0;" ::: "memory")

// Newton reciprocal (no MUFU): a >= 1 here.
__device__ __forceinline__ float rcp_nr(float a) {
    float r = __uint_as_float(0x7EF311C3u - __float_as_uint(a));
    r = r * fmaf(-a, r, 2.0f);
    r = r * fmaf(-a, r, 2.0f);
    r = r * fmaf(-a, r, 2.0f);
    return r;
}
__device__ __forceinline__ float nexp(float x) {  // exp(-clamp(x, +/-40))
    x = fminf(fmaxf(x, -40.f), 40.f);
    return expf(-x);
}
__device__ __forceinline__ uint32_t pack_bf2(float f0, float f1,
                                             uint32_t& lopack) {
    __nv_bfloat16 h0 = __float2bfloat16(f0), h1 = __float2bfloat16(f1);
    __nv_bfloat16 l0 = __float2bfloat16(f0 - __bfloat162float(h0));
    __nv_bfloat16 l1 = __float2bfloat16(f1 - __bfloat162float(h1));
    lopack = (uint32_t)__bfloat16_as_ushort(l0) |
             ((uint32_t)__bfloat16_as_ushort(l1) << 16);
    return (uint32_t)__bfloat16_as_ushort(h0) |
           ((uint32_t)__bfloat16_as_ushort(h1) << 16);
}

// ---------------------------------------------------------------------------
// Kernel 1: projections -> exp tables, plus fp32->bf16(hi,lo) of arg1/arg2.
// ---------------------------------------------------------------------------
__global__ __launch_bounds__(256) void proj_convert(
    const float* __restrict__ arg1, const float* __restrict__ arg2,
    const float* __restrict__ Wg, const float* __restrict__ V,
    const float* __restrict__ Bg) {
    extern __shared__ float wsm[];  // [0:8192) Wg^T [s][1024], [8192:16384) V^T
    for (int t = threadIdx.x; t < 8192; t += 256) {
        int d = t >> 3, s = t & 7;
        wsm[s * 1024 + d] = Wg[t];
        wsm[8192 + s * 1024 + d] = V[t];
    }
    __syncthreads();
    int w = threadIdx.x >> 5, lane = threadIdx.x & 31;
    int r = blockIdx.x * 8 + w;
    const float* a1 = arg1 + (size_t)r * D_;
    const float* a2 = arg2 + (size_t)r * D_;
    float aG1[8] = {}, aG2[8] = {}, aS1[8] = {}, aS2[8] = {};
#pragma unroll
    for (int t = 0; t < 16; t++) {
        int d = lane + t * 32;
        float v1 = a1[d], v2 = a2[d];
        __nv_bfloat16 h1 = __float2bfloat16(v1);
        g_A1h[(size_t)r * D_ + d] = h1;
        g_A1l[(size_t)r * D_ + d] = __float2bfloat16(v1 - __bfloat162float(h1));
        __nv_bfloat16 h2 = __float2bfloat16(v2);
        g_A2h[(size_t)r * D_ + d] = h2;
        g_A2l[(size_t)r * D_ + d] = __float2bfloat16(v2 - __bfloat162float(h2));
#pragma unroll
        for (int s = 0; s < 8; s++) {
            aG1[s] += v1 * wsm[s * 1024 + d];
            aG2[s] += v2 * wsm[s * 1024 + 512 + d];
            aS1[s] += v1 * wsm[8192 + s * 1024 + d];
            aS2[s] += v2 * wsm[8192 + s * 1024 + 512 + d];
        }
    }
#pragma unroll
    for (int m = 16; m; m >>= 1) {
#pragma unroll
        for (int s = 0; s < 8; s++) {
            aG1[s] += __shfl_xor_sync(0xffffffffu, aG1[s], m);
            aG2[s] += __shfl_xor_sync(0xffffffffu, aG2[s], m);
            aS1[s] += __shfl_xor_sync(0xffffffffu, aS1[s], m);
            aS2[s] += __shfl_xor_sync(0xffffffffu, aS2[s], m);
        }
    }
    if (lane == 0) {
#pragma unroll
        for (int s = 0; s < 8; s++) {
            g_EG1[r * 8 + s] = nexp(aG1[s]);
            g_EG2[r * 8 + s] = nexp(aG2[s] + Bg[s]);
            g_ES1[r * 8 + s] = nexp(aS1[s]);
            g_ES2[r * 8 + s] = nexp(aS2[s]);
        }
    }
}

// ---------------------------------------------------------------------------
// Kernel 2: Mr [k,d,e] -> transposed bf16 split Mt [k,e,d].
// ---------------------------------------------------------------------------
__global__ void mr_transpose(const float* __restrict__ Mr) {
    __shared__ float tile[32][33];
    int k = blockIdx.z;
    int d0 = blockIdx.y * 32, e0 = blockIdx.x * 32;
    const float* src = Mr + (size_t)k * D_ * D_;
    for (int rr = threadIdx.y; rr < 32; rr += 8)
        tile[rr][threadIdx.x] = src[(size_t)(d0 + rr) * D_ + e0 + threadIdx.x];
    __syncthreads();
    __nv_bfloat16* dh = g_Mth + (size_t)k * D_ * D_;
    __nv_bfloat16* dl = g_Mtl + (size_t)k * D_ * D_;
    for (int rr = threadIdx.y; rr < 32; rr += 8) {
        float v = tile[threadIdx.x][rr];
        __nv_bfloat16 h = __float2bfloat16(v);
        dh[(size_t)(e0 + rr) * D_ + d0 + threadIdx.x] = h;
        dl[(size_t)(e0 + rr) * D_ + d0 + threadIdx.x] =
            __float2bfloat16(v - __bfloat162float(h));
    }
}

// ---------------------------------------------------------------------------
// Kernel 3: P = arg1 @ Mr^T (split-bf16, 3 passes). CTA 128(M)x128(N), BK=32.
// 512 threads, 16 warps as 4M x 4N (warp tile 32x32), acc 32 regs.
// 3-stage cp.async pipeline. stage: Ah@0|Al@10240|Bh@20480|Bl@30720 = 40960.
// grid = (4, 128, 8), 1 CTA/SM (16 warps).
// ---------------------------------------------------------------------------
#define STG_P 40960u
__global__ __launch_bounds__(512, 1) void pmul_mma() {
    const int k = blockIdx.z, mB = blockIdx.y, nB = blockIdx.x;
    extern __shared__ char sm[];
    const uint32_t sb = smem_u32(sm);
    const int tid = threadIdx.x, wid = tid >> 5, lane = tid & 31;
    const int warpM = wid >> 2, warpN = wid & 3;

    const __nv_bfloat16* pAh = g_A1h + (size_t)mB * 128 * D_;
    const __nv_bfloat16* pAl = g_A1l + (size_t)mB * 128 * D_;
    const __nv_bfloat16* pBh = g_Mth + ((size_t)k * D_ + nB * 128) * D_;
    const __nv_bfloat16* pBl = g_Mtl + ((size_t)k * D_ + nB * 128) * D_;

    auto load_chunk = [&](int c, int buf) {
        uint32_t dstb = sb + (uint32_t)buf * STG_P;
#pragma unroll
        for (int rr = 0; rr < 4; rr++) {
            int op = tid + rr * 512;
            int tile = op >> 9;               // 0 Ah 1 Al 2 Bh 3 Bl
            int row = (op >> 2) & 127;
            int seg = op & 3;
            const __nv_bfloat16* g =
                (tile == 0) ? pAh : (tile == 1) ? pAl : (tile == 2) ? pBh : pBl;
            uint32_t off = (uint32_t)tile * 10240u + (uint32_t)(row * 80 + seg * 16);
            cp16(dstb + off, g + (size_t)row * D_ + c * 32 + seg * 8);
        }
    };

    float acc[2][4][4];
#pragma unroll
    for (int mt = 0; mt < 2; mt++)
#pragma unroll
        for (int nt = 0; nt < 4; nt++)
#pragma unroll
            for (int q = 0; q < 4; q++) acc[mt][nt][q] = 0.f;

    load_chunk(0, 0);
    CP_COMMIT();
    load_chunk(1, 1);
    CP_COMMIT();
    const int lm = lane & 15, lk = lane >> 4;
    const int bn = lane & 7, bk2 = (lane >> 3) & 1;

    for (int c = 0; c < 16; c++) {
        int buf = c % 3;
        if (c + 2 < 16) { load_chunk(c + 2, (c + 2) % 3); CP_COMMIT(); CP_WAIT2(); }
        else if (c + 1 < 16) CP_WAIT1();
        else CP_WAIT0();
        __syncthreads();
        uint32_t sbuf = sb + (uint32_t)buf * STG_P;
#pragma unroll
        for (int ks = 0; ks < 2; ks++) {
            uint32_t ah[2][4], al[2][4], bh[4][2], bl[4][2];
#pragma unroll
            for (int mt = 0; mt < 2; mt++) {
                uint32_t a = sbuf + (uint32_t)((warpM * 32 + mt * 16 + lm) * 80 +
                                               (ks * 16 + lk * 8) * 2);
                ldm_x4(ah[mt], a);
                ldm_x4(al[mt], a + 10240u);
            }
#pragma unroll
            for (int nt = 0; nt < 4; nt++) {
                uint32_t a = sbuf + 20480u +
                             (uint32_t)((warpN * 32 + nt * 8 + bn) * 80 +
                                        (ks * 16 + bk2 * 8) * 2);
                ldm_x2(bh[nt], a);
                ldm_x2(bl[nt], a + 10240u);
            }
#pragma unroll
            for (int mt = 0; mt < 2; mt++)
#pragma unroll
                for (int nt = 0; nt < 4; nt++) {
                    mma_bf16(acc[mt][nt], ah[mt], bh[nt]);
                    mma_bf16(acc[mt][nt], ah[mt], bl[nt]);
                    mma_bf16(acc[mt][nt], al[mt], bh[nt]);
                }
        }
        __syncthreads();
    }

    // epilogue: split to bf16 hi/lo and store P
    const int rowg0 = mB * 128 + warpM * 32;
#pragma unroll
    for (int mt = 0; mt < 2; mt++) {
#pragma unroll
        for (int half = 0; half < 2; half++) {
            int rowg = rowg0 + mt * 16 + (lane >> 2) + half * 8;
            int bb = rowg >> 9, ii = rowg & 511;
            size_t base = ((size_t)(bb * S_ + k) * L_ + ii) * D_ + nB * 128;
#pragma unroll
            for (int nt = 0; nt < 4; nt++) {
                int colg = warpN * 32 + nt * 8 + (lane & 3) * 2;
                uint32_t wl;
                uint32_t wh = pack_bf2(acc[mt][nt][half * 2],
                                       acc[mt][nt][half * 2 + 1], wl);
                *(uint32_t*)(g_Ph + base + colg) = wh;
                *(uint32_t*)(g_Pl + base + colg) = wl;
            }
        }
    }
}

// ---------------------------------------------------------------------------
// Kernel 4: per (b, i-tile 128, j-tile 64): loop k, bi = P @ arg2^T (split-bf16)
// + fused factored-sigmoid gating, final sigmoid. 8 warps as 4M x 2N.
// 3-stage pipeline: stage 30720, tables @92160. grid = (8, 4, 32). 2 CTAs/SM.
// ---------------------------------------------------------------------------
#define STG_S 30720u
__global__ __launch_bounds__(256, 2) void score_mma(
    const float* __restrict__ U, const float* __restrict__ bvec,
    float* __restrict__ out) {
    const int b = blockIdx.z;
    const int i0 = blockIdx.y * 128;
    const int j0 = blockIdx.x * 64;
    extern __shared__ char sm[];
    const uint32_t sb = smem_u32(sm);
    float* EG1t = (float*)(sm + 92160);   // [128][9]
    float* ES1t = (float*)(sm + 96768);   // [128][9]
    float* EG2t = (float*)(sm + 101376);  // [8][64]
    float* ES2t = (float*)(sm + 103424);  // [8][64]
    const int tid = threadIdx.x, wid = tid >> 5, lane = tid & 31;
    const int warpM = wid >> 1, warpN = wid & 1;

    for (int t = tid; t < 1024; t += 256) {
        int r = t >> 3, s = t & 7;
        EG1t[r * 9 + s] = g_EG1[(size_t)(b * L_ + i0 + r) * 8 + s];
        ES1t[r * 9 + s] = g_ES1[(size_t)(b * L_ + i0 + r) * 8 + s];
    }
    for (int t = tid; t < 512; t += 256) {
        int kk = t >> 6, j = t & 63;
        EG2t[kk * 64 + j] = g_EG2[(size_t)(b * L_ + j0 + j) * 8 + kk];
        ES2t[kk * 64 + j] = g_ES2[(size_t)(b * L_ + j0 + j) * 8 + kk];
    }

    float Ur[8];
#pragma unroll
    for (int s = 0; s < 8; s++) Ur[s] = __ldg(U + s);
    float c0 = 0.f;
#pragma unroll
    for (int s = 0; s < 8; s++) c0 += Ur[s] * __ldg(bvec + s);

    const __nv_bfloat16* pBh = g_A2h + (size_t)(b * L_ + j0) * D_;
    const __nv_bfloat16* pBl = g_A2l + (size_t)(b * L_ + j0) * D_;

    auto load_chunk = [&](int cc, int buf) {
        int k = cc >> 4, c = cc & 15;
        const __nv_bfloat16* pAh = g_Ph + ((size_t)(b * S_ + k) * L_ + i0) * D_;
        const __nv_bfloat16* pAl = g_Pl + ((size_t)(b * S_ + k) * L_ + i0) * D_;
        uint32_t dstb = sb + (uint32_t)buf * STG_S;
#pragma unroll
        for (int rr = 0; rr < 2; rr++) {
            int op = tid + rr * 256;
            int row = op >> 2, seg = op & 3;
            uint32_t off = (uint32_t)(row * 80 + seg * 16);
            size_t gi = (size_t)row * D_ + c * 32 + seg * 8;
            cp16(dstb + off, pAh + gi);
            cp16(dstb + 10240u + off, pAl + gi);
        }
        {
            int row = tid >> 2, seg = tid & 3;
            uint32_t off = (uint32_t)(row * 80 + seg * 16);
            size_t gi = (size_t)row * D_ + c * 32 + seg * 8;
            cp16(dstb + 20480u + off, pBh + gi);
            cp16(dstb + 25600u + off, pBl + gi);
        }
    };

    float acc[2][4][4], part[2][4][4];
#pragma unroll
    for (int mt = 0; mt < 2; mt++)
#pragma unroll
        for (int nt = 0; nt < 4; nt++)
#pragma unroll
            for (int q = 0; q < 4; q++) part[mt][nt][q] = 0.f;

    load_chunk(0, 0);
    CP_COMMIT();
    load_chunk(1, 1);
    CP_COMMIT();
    const int lm = lane & 15, lk = lane >> 4;
    const int bn = lane & 7, bk2 = (lane >> 3) & 1;

    for (int cc = 0; cc < 128; cc++) {
        int k = cc >> 4, c = cc & 15, buf = cc % 3;
        if (cc + 2 < 128) { load_chunk(cc + 2, (cc + 2) % 3); CP_COMMIT(); CP_WAIT2(); }
        else if (cc + 1 < 128) CP_WAIT1();
        else CP_WAIT0();
        __syncthreads();
        if (c == 0) {
#pragma unroll
            for (int mt = 0; mt < 2; mt++)
#pragma unroll
                for (int nt = 0; nt < 4; nt++)
#pragma unroll
                    for (int q = 0; q < 4; q++) acc[mt][nt][q] = 0.f;
        }
        uint32_t sbuf = sb + (uint32_t)buf * STG_S;
#pragma unroll
        for (int ks = 0; ks < 2; ks++) {
            uint32_t ah[2][4], al[2][4], bh[4][2], bl[4][2];
#pragma unroll
            for (int mt = 0; mt < 2; mt++) {
                uint32_t a = sbuf + (uint32_t)((warpM * 32 + mt * 16 + lm) * 80 +
                                               (ks * 16 + lk * 8) * 2);
                ldm_x4(ah[mt], a);
                ldm_x4(al[mt], a + 10240u);
            }
#pragma unroll
            for (int nt = 0; nt < 4; nt++) {
                uint32_t a = sbuf + 20480u +
                             (uint32_t)((warpN * 32 + nt * 8 + bn) * 80 +
                                        (ks * 16 + bk2 * 8) * 2);
                ldm_x2(bh[nt], a);
                ldm_x2(bl[nt], a + 5120u);
            }
#pragma unroll
            for (int mt = 0; mt < 2; mt++)
#pragma unroll
                for (int nt = 0; nt < 4; nt++) {
                    mma_bf16(acc[mt][nt], ah[mt], bh[nt]);
                    mma_bf16(acc[mt][nt], ah[mt], bl[nt]);
                    mma_bf16(acc[mt][nt], al[mt], bh[nt]);
                }
        }
        if (c == 15) {
            float Uk = Ur[k];
#pragma unroll
            for (int mt = 0; mt < 2; mt++) {
                int r0 = warpM * 32 + mt * 16 + (lane >> 2);
                float eg1a = EG1t[r0 * 9 + k], es1a = ES1t[r0 * 9 + k];
                float eg1b = EG1t[(r0 + 8) * 9 + k], es1b = ES1t[(r0 + 8) * 9 + k];
#pragma unroll
                for (int nt = 0; nt < 4; nt++) {
                    int jj = warpN * 32 + nt * 8 + (lane & 3) * 2;
                    float eg2x = EG2t[k * 64 + jj], eg2y = EG2t[k * 64 + jj + 1];
                    float es2x = ES2t[k * 64 + jj], es2y = ES2t[k * 64 + jj + 1];
                    float g, s;
                    g = rcp_nr(fmaf(eg1a, eg2x, 1.f));
                    s = rcp_nr(fmaf(es1a, es2x, 1.f));
                    part[mt][nt][0] =
                        fmaf(Uk, fmaf(g, acc[mt][nt][0] - s, s), part[mt][nt][0]);
                    g = rcp_nr(fmaf(eg1a, eg2y, 1.f));
                    s = rcp_nr(fmaf(es1a, es2y, 1.f));
                    part[mt][nt][1] =
                        fmaf(Uk, fmaf(g, acc[mt][nt][1] - s, s), part[mt][nt][1]);
                    g = rcp_nr(fmaf(eg1b, eg2x, 1.f));
                    s = rcp_nr(fmaf(es1b, es2x, 1.f));
                    part[mt][nt][2] =
                        fmaf(Uk, fmaf(g, acc[mt][nt][2] - s, s), part[mt][nt][2]);
                    g = rcp_nr(fmaf(eg1b, eg2y, 1.f));
                    s = rcp_nr(fmaf(es1b, es2y, 1.f));
                    part[mt][nt][3] =
                        fmaf(Uk, fmaf(g, acc[mt][nt][3] - s, s), part[mt][nt][3]);
                }
            }
        }
        __syncthreads();
    }

    // final sigmoid + store
#pragma unroll
    for (int mt = 0; mt < 2; mt++) {
        int ibase = i0 + warpM * 32 + mt * 16 + (lane >> 2);
#pragma unroll
        for (int half = 0; half < 2; half++) {
            float* orow = out + ((size_t)b * L_ + ibase + half * 8) * L_ + j0;
#pragma unroll
            for (int nt = 0; nt < 4; nt++) {
                int jj = warpN * 32 + nt * 8 + (lane & 3) * 2;
                float z0 = part[mt][nt][half * 2 + 0] + c0;
                float z1 = part[mt][nt][half * 2 + 1] + c0;
                float2 v;
                v.x = rcp_nr(1.f + __expf(-z0));
                v.y = rcp_nr(1.f + __expf(-z1));
                *(float2*)(orow + jj) = v;
            }
        }
    }
}

// ---------------------------------------------------------------------------
extern "C" void kernel_launch(void* const* d_in, const int* in_sizes, int n_in,
                              void* d_out, int out_size) {
    const float* arg1 = (const float*)d_in[0];
    const float* arg2 = (const float*)d_in[1];
    const float* Wg   = (const float*)d_in[2];
    const float* Bg   = (const float*)d_in[3];
    const float* Mr   = (const float*)d_in[4];
    const float* V    = (const float*)d_in[5];
    const float* bvec = (const float*)d_in[6];
    const float* U    = (const float*)d_in[7];
    float* out = (float*)d_out;
    (void)in_sizes; (void)n_in; (void)out_size;

    const int SMEM_PROJ = 65536;
    const int SMEM_B = 3 * 40960;            // 122880
    const int SMEM_C = 3 * 30720 + 13312;    // 105472
    cudaFuncSetAttribute(proj_convert, cudaFuncAttributeMaxDynamicSharedMemorySize, SMEM_PROJ);
    cudaFuncSetAttribute(pmul_mma, cudaFuncAttributeMaxDynamicSharedMemorySize, SMEM_B);
    cudaFuncSetAttribute(score_mma, cudaFuncAttributeMaxDynamicSharedMemorySize, SMEM_C);

    proj_convert<<<BL_ / 8, 256, SMEM_PROJ>>>(arg1, arg2, Wg, V, Bg);
    mr_transpose<<<dim3(16, 16, 8), dim3(32, 8)>>>(Mr);
    pmul_mma<<<dim3(4, 128, 8), 512, SMEM_B>>>();
    score_mma<<<dim3(8, 4, 32), 256, SMEM_C>>>(U, bvec, out);
}

// round 16
// speedup vs baseline: 1.5451x; 1.0335x over previous
#include <cuda_runtime.h>
#include <cuda_bf16.h>
#include <cstdint>

#define B_ 32
#define L_ 512
#define D_ 512
#define S_ 8
#define BL_ (B_ * L_)

// ---------------- static device scratch ----------------
__device__ __nv_bfloat16 g_A1h[(size_t)BL_ * D_];
__device__ __nv_bfloat16 g_A1l[(size_t)BL_ * D_];
__device__ __nv_bfloat16 g_A2h[(size_t)BL_ * D_];
__device__ __nv_bfloat16 g_A2l[(size_t)BL_ * D_];
__device__ __nv_bfloat16 g_Mth[(size_t)S_ * D_ * D_];  // Mr^T [k][e][d]
__device__ __nv_bfloat16 g_Mtl[(size_t)S_ * D_ * D_];
__device__ __nv_bfloat16 g_Ph[(size_t)B_ * S_ * L_ * D_];  // P [b,k,i,e]
__device__ __nv_bfloat16 g_Pl[(size_t)B_ * S_ * L_ * D_];
// factored sigmoid tables: exp(-g1), exp(-(g2+Bg)), exp(-s1), exp(-s2)
__device__ float g_EG1[BL_ * S_], g_EG2[BL_ * S_], g_ES1[BL_ * S_], g_ES2[BL_ * S_];

// ---------------- helpers ----------------
__device__ __forceinline__ uint32_t smem_u32(const void* p) {
    return (uint32_t)__cvta_generic_to_shared(p);
}
__device__ __forceinline__ void ldm_x4(uint32_t* r, uint32_t a) {
    asm volatile("ldmatrix.sync.aligned.m8n8.x4.shared.b16 {%0,%1,%2,%3}, [%4];"
                 : "=r"(r[0]), "=r"(r[1]), "=r"(r[2]), "=r"(r[3]) : "r"(a));
}
__device__ __forceinline__ void mma_bf16(float* d, const uint32_t* a, const uint32_t* b) {
    asm volatile(
        "mma.sync.aligned.m16n8k16.row.col.f32.bf16.bf16.f32 "
        "{%0,%1,%2,%3},{%4,%5,%6,%7},{%8,%9},{%0,%1,%2,%3};"
        : "+f"(d[0]), "+f"(d[1]), "+f"(d[2]), "+f"(d[3])
        : "r"(a[0]), "r"(a[1]), "r"(a[2]), "r"(a[3]), "r"(b[0]), "r"(b[1]));
}
__device__ __forceinline__ void cp16(uint32_t dst, const void* src) {
    asm volatile("cp.async.cg.shared.global [%0], [%1], 16;" ::"r"(dst), "l"(src));
}
#define CP_COMMIT() asm volatile("cp.async.commit_group;" ::: "memory")
#define CP_WAIT2() asm volatile("cp.async.wait_group 2;" ::: "memory")
#define CP_WAIT1() asm volatile("cp.async.wait_group 1;" ::: "memory")
#define CP_WAIT0() asm volatile("cp.async.wait_group 0;" ::: "memory")

// Newton reciprocal (no MUFU): a >= 1 here.
__device__ __forceinline__ float rcp_nr(float a) {
    float r = __uint_as_float(0x7EF311C3u - __float_as_uint(a));
    r = r * fmaf(-a, r, 2.0f);
    r = r * fmaf(-a, r, 2.0f);
    r = r * fmaf(-a, r, 2.0f);
    return r;
}
__device__ __forceinline__ float nexp(float x) {  // exp(-clamp(x, +/-40))
    x = fminf(fmaxf(x, -40.f), 40.f);
    return expf(-x);
}
__device__ __forceinline__ uint32_t pack_bf2(float f0, float f1,
                                             uint32_t& lopack) {
    __nv_bfloat16 h0 = __float2bfloat16(f0), h1 = __float2bfloat16(f1);
    __nv_bfloat16 l0 = __float2bfloat16(f0 - __bfloat162float(h0));
    __nv_bfloat16 l1 = __float2bfloat16(f1 - __bfloat162float(h1));
    lopack = (uint32_t)__bfloat16_as_ushort(l0) |
             ((uint32_t)__bfloat16_as_ushort(l1) << 16);
    return (uint32_t)__bfloat16_as_ushort(h0) |
           ((uint32_t)__bfloat16_as_ushort(h1) << 16);
}

// ---------------------------------------------------------------------------
// Kernel 1: projections -> exp tables, plus fp32->bf16(hi,lo) of arg1/arg2.
// ---------------------------------------------------------------------------
__global__ __launch_bounds__(256) void proj_convert(
    const float* __restrict__ arg1, const float* __restrict__ arg2,
    const float* __restrict__ Wg, const float* __restrict__ V,
    const float* __restrict__ Bg) {
    extern __shared__ float wsm[];  // [0:8192) Wg^T [s][1024], [8192:16384) V^T
    for (int t = threadIdx.x; t < 8192; t += 256) {
        int d = t >> 3, s = t & 7;
        wsm[s * 1024 + d] = Wg[t];
        wsm[8192 + s * 1024 + d] = V[t];
    }
    __syncthreads();
    int w = threadIdx.x >> 5, lane = threadIdx.x & 31;
    int r = blockIdx.x * 8 + w;
    const float* a1 = arg1 + (size_t)r * D_;
    const float* a2 = arg2 + (size_t)r * D_;
    float aG1[8] = {}, aG2[8] = {}, aS1[8] = {}, aS2[8] = {};
#pragma unroll
    for (int t = 0; t < 16; t++) {
        int d = lane + t * 32;
        float v1 = a1[d], v2 = a2[d];
        __nv_bfloat16 h1 = __float2bfloat16(v1);
        g_A1h[(size_t)r * D_ + d] = h1;
        g_A1l[(size_t)r * D_ + d] = __float2bfloat16(v1 - __bfloat162float(h1));
        __nv_bfloat16 h2 = __float2bfloat16(v2);
        g_A2h[(size_t)r * D_ + d] = h2;
        g_A2l[(size_t)r * D_ + d] = __float2bfloat16(v2 - __bfloat162float(h2));
#pragma unroll
        for (int s = 0; s < 8; s++) {
            aG1[s] += v1 * wsm[s * 1024 + d];
            aG2[s] += v2 * wsm[s * 1024 + 512 + d];
            aS1[s] += v1 * wsm[8192 + s * 1024 + d];
            aS2[s] += v2 * wsm[8192 + s * 1024 + 512 + d];
        }
    }
#pragma unroll
    for (int m = 16; m; m >>= 1) {
#pragma unroll
        for (int s = 0; s < 8; s++) {
            aG1[s] += __shfl_xor_sync(0xffffffffu, aG1[s], m);
            aG2[s] += __shfl_xor_sync(0xffffffffu, aG2[s], m);
            aS1[s] += __shfl_xor_sync(0xffffffffu, aS1[s], m);
            aS2[s] += __shfl_xor_sync(0xffffffffu, aS2[s], m);
        }
    }
    if (lane == 0) {
#pragma unroll
        for (int s = 0; s < 8; s++) {
            g_EG1[r * 8 + s] = nexp(aG1[s]);
            g_EG2[r * 8 + s] = nexp(aG2[s] + Bg[s]);
            g_ES1[r * 8 + s] = nexp(aS1[s]);
            g_ES2[r * 8 + s] = nexp(aS2[s]);
        }
    }
}

// ---------------------------------------------------------------------------
// Kernel 2: Mr [k,d,e] -> transposed bf16 split Mt [k,e,d].
// ---------------------------------------------------------------------------
__global__ void mr_transpose(const float* __restrict__ Mr) {
    __shared__ float tile[32][33];
    int k = blockIdx.z;
    int d0 = blockIdx.y * 32, e0 = blockIdx.x * 32;
    const float* src = Mr + (size_t)k * D_ * D_;
    for (int rr = threadIdx.y; rr < 32; rr += 8)
        tile[rr][threadIdx.x] = src[(size_t)(d0 + rr) * D_ + e0 + threadIdx.x];
    __syncthreads();
    __nv_bfloat16* dh = g_Mth + (size_t)k * D_ * D_;
    __nv_bfloat16* dl = g_Mtl + (size_t)k * D_ * D_;
    for (int rr = threadIdx.y; rr < 32; rr += 8) {
        float v = tile[threadIdx.x][rr];
        __nv_bfloat16 h = __float2bfloat16(v);
        dh[(size_t)(e0 + rr) * D_ + d0 + threadIdx.x] = h;
        dl[(size_t)(e0 + rr) * D_ + d0 + threadIdx.x] =
            __float2bfloat16(v - __bfloat162float(h));
    }
}

// ---------------------------------------------------------------------------
// Kernel 3: P = arg1 @ Mr^T (split-bf16, 3 passes). CTA 128(M)x128(N), BK=32.
// 512 threads, 16 warps as 4M x 4N (warp tile 32x32), acc 32 regs.
// 3-stage cp.async pipeline. Pass-ordered MMA (8 indep accs between reuse),
// B loaded with ldmatrix.x4 (nt pairs).
// ---------------------------------------------------------------------------
#define STG_P 40960u
__global__ __launch_bounds__(512, 1) void pmul_mma() {
    const int k = blockIdx.z, mB = blockIdx.y, nB = blockIdx.x;
    extern __shared__ char sm[];
    const uint32_t sb = smem_u32(sm);
    const int tid = threadIdx.x, wid = tid >> 5, lane = tid & 31;
    const int warpM = wid >> 2, warpN = wid & 3;

    const __nv_bfloat16* pAh = g_A1h + (size_t)mB * 128 * D_;
    const __nv_bfloat16* pAl = g_A1l + (size_t)mB * 128 * D_;
    const __nv_bfloat16* pBh = g_Mth + ((size_t)k * D_ + nB * 128) * D_;
    const __nv_bfloat16* pBl = g_Mtl + ((size_t)k * D_ + nB * 128) * D_;

    auto load_chunk = [&](int c, int buf) {
        uint32_t dstb = sb + (uint32_t)buf * STG_P;
#pragma unroll
        for (int rr = 0; rr < 4; rr++) {
            int op = tid + rr * 512;
            int tile = op >> 9;               // 0 Ah 1 Al 2 Bh 3 Bl
            int row = (op >> 2) & 127;
            int seg = op & 3;
            const __nv_bfloat16* g =
                (tile == 0) ? pAh : (tile == 1) ? pAl : (tile == 2) ? pBh : pBl;
            uint32_t off = (uint32_t)tile * 10240u + (uint32_t)(row * 80 + seg * 16);
            cp16(dstb + off, g + (size_t)row * D_ + c * 32 + seg * 8);
        }
    };

    float acc[2][4][4];
#pragma unroll
    for (int mt = 0; mt < 2; mt++)
#pragma unroll
        for (int nt = 0; nt < 4; nt++)
#pragma unroll
            for (int q = 0; q < 4; q++) acc[mt][nt][q] = 0.f;

    load_chunk(0, 0);
    CP_COMMIT();
    load_chunk(1, 1);
    CP_COMMIT();
    const int lm = lane & 15, lk = lane >> 4;
    // B x4 lane map: bit4 -> nt-in-pair, bit3 -> k-half, bits0-2 -> row
    const int bp_row = ((lane >> 4) & 1) * 8 + (lane & 7);
    const int bp_k = (lane >> 3) & 1;

    for (int c = 0; c < 16; c++) {
        int buf = c % 3;
        if (c + 2 < 16) { load_chunk(c + 2, (c + 2) % 3); CP_COMMIT(); CP_WAIT2(); }
        else if (c + 1 < 16) CP_WAIT1();
        else CP_WAIT0();
        __syncthreads();
        uint32_t sbuf = sb + (uint32_t)buf * STG_P;
#pragma unroll
        for (int ks = 0; ks < 2; ks++) {
            uint32_t ah[2][4], al[2][4], bh[4][2], bl[4][2];
#pragma unroll
            for (int mt = 0; mt < 2; mt++) {
                uint32_t a = sbuf + (uint32_t)((warpM * 32 + mt * 16 + lm) * 80 +
                                               (ks * 16 + lk * 8) * 2);
                ldm_x4(ah[mt], a);
                ldm_x4(al[mt], a + 10240u);
            }
#pragma unroll
            for (int p = 0; p < 2; p++) {
                uint32_t a = sbuf + 20480u +
                             (uint32_t)((warpN * 32 + p * 16 + bp_row) * 80 +
                                        (ks * 16 + bp_k * 8) * 2);
                uint32_t t4[4];
                ldm_x4(t4, a);
                bh[2 * p][0] = t4[0]; bh[2 * p][1] = t4[1];
                bh[2 * p + 1][0] = t4[2]; bh[2 * p + 1][1] = t4[3];
                ldm_x4(t4, a + 10240u);
                bl[2 * p][0] = t4[0]; bl[2 * p][1] = t4[1];
                bl[2 * p + 1][0] = t4[2]; bl[2 * p + 1][1] = t4[3];
            }
            // pass-ordered: 8 independent accs between same-acc reuse
#pragma unroll
            for (int mt = 0; mt < 2; mt++)
#pragma unroll
                for (int nt = 0; nt < 4; nt++) mma_bf16(acc[mt][nt], ah[mt], bh[nt]);
#pragma unroll
            for (int mt = 0; mt < 2; mt++)
#pragma unroll
                for (int nt = 0; nt < 4; nt++) mma_bf16(acc[mt][nt], ah[mt], bl[nt]);
#pragma unroll
            for (int mt = 0; mt < 2; mt++)
#pragma unroll
                for (int nt = 0; nt < 4; nt++) mma_bf16(acc[mt][nt], al[mt], bh[nt]);
        }
        __syncthreads();
    }

    // epilogue: split to bf16 hi/lo and store P
    const int rowg0 = mB * 128 + warpM * 32;
#pragma unroll
    for (int mt = 0; mt < 2; mt++) {
#pragma unroll
        for (int half = 0; half < 2; half++) {
            int rowg = rowg0 + mt * 16 + (lane >> 2) + half * 8;
            int bb = rowg >> 9, ii = rowg & 511;
            size_t base = ((size_t)(bb * S_ + k) * L_ + ii) * D_ + nB * 128;
#pragma unroll
            for (int nt = 0; nt < 4; nt++) {
                int colg = warpN * 32 + nt * 8 + (lane & 3) * 2;
                uint32_t wl;
                uint32_t wh = pack_bf2(acc[mt][nt][half * 2],
                                       acc[mt][nt][half * 2 + 1], wl);
                *(uint32_t*)(g_Ph + base + colg) = wh;
                *(uint32_t*)(g_Pl + base + colg) = wl;
            }
        }
    }
}

// ---------------------------------------------------------------------------
// Kernel 4: per (b, i-tile 128, j-tile 64): loop k, bi = P @ arg2^T (split-bf16)
// + fused factored-sigmoid gating, final sigmoid. 8 warps as 4M x 2N.
// 3-stage pipeline; pass-ordered MMA; B via ldmatrix.x4. 2 CTAs/SM.
// ---------------------------------------------------------------------------
#define STG_S 30720u
__global__ __launch_bounds__(256, 2) void score_mma(
    const float* __restrict__ U, const float* __restrict__ bvec,
    float* __restrict__ out) {
    const int b = blockIdx.z;
    const int i0 = blockIdx.y * 128;
    const int j0 = blockIdx.x * 64;
    extern __shared__ char sm[];
    const uint32_t sb = smem_u32(sm);
    float* EG1t = (float*)(sm + 92160);   // [128][9]
    float* ES1t = (float*)(sm + 96768);   // [128][9]
    float* EG2t = (float*)(sm + 101376);  // [8][64]
    float* ES2t = (float*)(sm + 103424);  // [8][64]
    const int tid = threadIdx.x, wid = tid >> 5, lane = tid & 31;
    const int warpM = wid >> 1, warpN = wid & 1;

    for (int t = tid; t < 1024; t += 256) {
        int r = t >> 3, s = t & 7;
        EG1t[r * 9 + s] = g_EG1[(size_t)(b * L_ + i0 + r) * 8 + s];
        ES1t[r * 9 + s] = g_ES1[(size_t)(b * L_ + i0 + r) * 8 + s];
    }
    for (int t = tid; t < 512; t += 256) {
        int kk = t >> 6, j = t & 63;
        EG2t[kk * 64 + j] = g_EG2[(size_t)(b * L_ + j0 + j) * 8 + kk];
        ES2t[kk * 64 + j] = g_ES2[(size_t)(b * L_ + j0 + j) * 8 + kk];
    }

    float Ur[8];
#pragma unroll
    for (int s = 0; s < 8; s++) Ur[s] = __ldg(U + s);
    float c0 = 0.f;
#pragma unroll
    for (int s = 0; s < 8; s++) c0 += Ur[s] * __ldg(bvec + s);

    const __nv_bfloat16* pBh = g_A2h + (size_t)(b * L_ + j0) * D_;
    const __nv_bfloat16* pBl = g_A2l + (size_t)(b * L_ + j0) * D_;

    auto load_chunk = [&](int cc, int buf) {
        int k = cc >> 4, c = cc & 15;
        const __nv_bfloat16* pAh = g_Ph + ((size_t)(b * S_ + k) * L_ + i0) * D_;
        const __nv_bfloat16* pAl = g_Pl + ((size_t)(b * S_ + k) * L_ + i0) * D_;
        uint32_t dstb = sb + (uint32_t)buf * STG_S;
#pragma unroll
        for (int rr = 0; rr < 2; rr++) {
            int op = tid + rr * 256;
            int row = op >> 2, seg = op & 3;
            uint32_t off = (uint32_t)(row * 80 + seg * 16);
            size_t gi = (size_t)row * D_ + c * 32 + seg * 8;
            cp16(dstb + off, pAh + gi);
            cp16(dstb + 10240u + off, pAl + gi);
        }
        {
            int row = tid >> 2, seg = tid & 3;
            uint32_t off = (uint32_t)(row * 80 + seg * 16);
            size_t gi = (size_t)row * D_ + c * 32 + seg * 8;
            cp16(dstb + 20480u + off, pBh + gi);
            cp16(dstb + 25600u + off, pBl + gi);
        }
    };

    float acc[2][4][4], part[2][4][4];
#pragma unroll
    for (int mt = 0; mt < 2; mt++)
#pragma unroll
        for (int nt = 0; nt < 4; nt++)
#pragma unroll
            for (int q = 0; q < 4; q++) part[mt][nt][q] = 0.f;

    load_chunk(0, 0);
    CP_COMMIT();
    load_chunk(1, 1);
    CP_COMMIT();
    const int lm = lane & 15, lk = lane >> 4;
    const int bp_row = ((lane >> 4) & 1) * 8 + (lane & 7);
    const int bp_k = (lane >> 3) & 1;

    for (int cc = 0; cc < 128; cc++) {
        int k = cc >> 4, c = cc & 15, buf = cc % 3;
        if (cc + 2 < 128) { load_chunk(cc + 2, (cc + 2) % 3); CP_COMMIT(); CP_WAIT2(); }
        else if (cc + 1 < 128) CP_WAIT1();
        else CP_WAIT0();
        __syncthreads();
        if (c == 0) {
#pragma unroll
            for (int mt = 0; mt < 2; mt++)
#pragma unroll
                for (int nt = 0; nt < 4; nt++)
#pragma unroll
                    for (int q = 0; q < 4; q++) acc[mt][nt][q] = 0.f;
        }
        uint32_t sbuf = sb + (uint32_t)buf * STG_S;
#pragma unroll
        for (int ks = 0; ks < 2; ks++) {
            uint32_t ah[2][4], al[2][4], bh[4][2], bl[4][2];
#pragma unroll
            for (int mt = 0; mt < 2; mt++) {
                uint32_t a = sbuf + (uint32_t)((warpM * 32 + mt * 16 + lm) * 80 +
                                               (ks * 16 + lk * 8) * 2);
                ldm_x4(ah[mt], a);
                ldm_x4(al[mt], a + 10240u);
            }
#pragma unroll
            for (int p = 0; p < 2; p++) {
                uint32_t a = sbuf + 20480u +
                             (uint32_t)((warpN * 32 + p * 16 + bp_row) * 80 +
                                        (ks * 16 + bp_k * 8) * 2);
                uint32_t t4[4];
                ldm_x4(t4, a);
                bh[2 * p][0] = t4[0]; bh[2 * p][1] = t4[1];
                bh[2 * p + 1][0] = t4[2]; bh[2 * p + 1][1] = t4[3];
                ldm_x4(t4, a + 5120u);
                bl[2 * p][0] = t4[0]; bl[2 * p][1] = t4[1];
                bl[2 * p + 1][0] = t4[2]; bl[2 * p + 1][1] = t4[3];
            }
            // pass-ordered: 8 independent accs between same-acc reuse
#pragma unroll
            for (int mt = 0; mt < 2; mt++)
#pragma unroll
                for (int nt = 0; nt < 4; nt++) mma_bf16(acc[mt][nt], ah[mt], bh[nt]);
#pragma unroll
            for (int mt = 0; mt < 2; mt++)
#pragma unroll
                for (int nt = 0; nt < 4; nt++) mma_bf16(acc[mt][nt], ah[mt], bl[nt]);
#pragma unroll
            for (int mt = 0; mt < 2; mt++)
#pragma unroll
                for (int nt = 0; nt < 4; nt++) mma_bf16(acc[mt][nt], al[mt], bh[nt]);
        }
        if (c == 15) {
            float Uk = Ur[k];
#pragma unroll
            for (int mt = 0; mt < 2; mt++) {
                int r0 = warpM * 32 + mt * 16 + (lane >> 2);
                float eg1a = EG1t[r0 * 9 + k], es1a = ES1t[r0 * 9 + k];
                float eg1b = EG1t[(r0 + 8) * 9 + k], es1b = ES1t[(r0 + 8) * 9 + k];
#pragma unroll
                for (int nt = 0; nt < 4; nt++) {
                    int jj = warpN * 32 + nt * 8 + (lane & 3) * 2;
                    float eg2x = EG2t[k * 64 + jj], eg2y = EG2t[k * 64 + jj + 1];
                    float es2x = ES2t[k * 64 + jj], es2y = ES2t[k * 64 + jj + 1];
                    float g, s;
                    g = rcp_nr(fmaf(eg1a, eg2x, 1.f));
                    s = rcp_nr(fmaf(es1a, es2x, 1.f));
                    part[mt][nt][0] =
                        fmaf(Uk, fmaf(g, acc[mt][nt][0] - s, s), part[mt][nt][0]);
                    g = rcp_nr(fmaf(eg1a, eg2y, 1.f));
                    s = rcp_nr(fmaf(es1a, es2y, 1.f));
                    part[mt][nt][1] =
                        fmaf(Uk, fmaf(g, acc[mt][nt][1] - s, s), part[mt][nt][1]);
                    g = rcp_nr(fmaf(eg1b, eg2x, 1.f));
                    s = rcp_nr(fmaf(es1b, es2x, 1.f));
                    part[mt][nt][2] =
                        fmaf(Uk, fmaf(g, acc[mt][nt][2] - s, s), part[mt][nt][2]);
                    g = rcp_nr(fmaf(eg1b, eg2y, 1.f));
                    s = rcp_nr(fmaf(es1b, es2y, 1.f));
                    part[mt][nt][3] =
                        fmaf(Uk, fmaf(g, acc[mt][nt][3] - s, s), part[mt][nt][3]);
                }
            }
        }
        __syncthreads();
    }

    // final sigmoid + store
#pragma unroll
    for (int mt = 0; mt < 2; mt++) {
        int ibase = i0 + warpM * 32 + mt * 16 + (lane >> 2);
#pragma unroll
        for (int half = 0; half < 2; half++) {
            float* orow = out + ((size_t)b * L_ + ibase + half * 8) * L_ + j0;
#pragma unroll
            for (int nt = 0; nt < 4; nt++) {
                int jj = warpN * 32 + nt * 8 + (lane & 3) * 2;
                float z0 = part[mt][nt][half * 2 + 0] + c0;
                float z1 = part[mt][nt][half * 2 + 1] + c0;
                float2 v;
                v.x = rcp_nr(1.f + __expf(-z0));
                v.y = rcp_nr(1.f + __expf(-z1));
                *(float2*)(orow + jj) = v;
            }
        }
    }
}

// ---------------------------------------------------------------------------
extern "C" void kernel_launch(void* const* d_in, const int* in_sizes, int n_in,
                              void* d_out, int out_size) {
    const float* arg1 = (const float*)d_in[0];
    const float* arg2 = (const float*)d_in[1];
    const float* Wg   = (const float*)d_in[2];
    const float* Bg   = (const float*)d_in[3];
    const float* Mr   = (const float*)d_in[4];
    const float* V    = (const float*)d_in[5];
    const float* bvec = (const float*)d_in[6];
    const float* U    = (const float*)d_in[7];
    float* out = (float*)d_out;
    (void)in_sizes; (void)n_in; (void)out_size;

    const int SMEM_PROJ = 65536;
    const int SMEM_B = 3 * 40960;            // 122880
    const int SMEM_C = 3 * 30720 + 13312;    // 105472
    cudaFuncSetAttribute(proj_convert, cudaFuncAttributeMaxDynamicSharedMemorySize, SMEM_PROJ);
    cudaFuncSetAttribute(pmul_mma, cudaFuncAttributeMaxDynamicSharedMemorySize, SMEM_B);
    cudaFuncSetAttribute(score_mma, cudaFuncAttributeMaxDynamicSharedMemorySize, SMEM_C);

    proj_convert<<<BL_ / 8, 256, SMEM_PROJ>>>(arg1, arg2, Wg, V, Bg);
    mr_transpose<<<dim3(16, 16, 8), dim3(32, 8)>>>(Mr);
    pmul_mma<<<dim3(4, 128, 8), 512, SMEM_B>>>();
    score_mma<<<dim3(8, 4, 32), 256, SMEM_C>>>(U, bvec, out);
}

// round 17
// speedup vs baseline: 2.1503x; 1.3917x over previous
#include <cuda_runtime.h>
#include <cuda_fp16.h>
#include <cstdint>

#define B_ 32
#define L_ 512
#define D_ 512
#define S_ 8
#define BL_ (B_ * L_)

// ---------------- static device scratch ----------------
__device__ __half g_A1h[(size_t)BL_ * D_];                 // arg1 fp16 (single)
__device__ __half g_A2h[(size_t)BL_ * D_];                 // arg2 fp16 hi
__device__ __half g_A2l[(size_t)BL_ * D_];                 // arg2 fp16 lo
__device__ __half g_Mth[(size_t)S_ * D_ * D_];             // Mr^T fp16 hi
__device__ __half g_Mtl[(size_t)S_ * D_ * D_];             // Mr^T fp16 lo
__device__ __half g_Ph[(size_t)B_ * S_ * L_ * D_];         // P fp16 (single)
// factored sigmoid tables: exp(-g1), exp(-(g2+Bg)), exp(-s1), exp(-s2)
__device__ float g_EG1[BL_ * S_], g_EG2[BL_ * S_], g_ES1[BL_ * S_], g_ES2[BL_ * S_];

// ---------------- helpers ----------------
__device__ __forceinline__ uint32_t smem_u32(const void* p) {
    return (uint32_t)__cvta_generic_to_shared(p);
}
__device__ __forceinline__ void ldm_x4(uint32_t* r, uint32_t a) {
    asm volatile("ldmatrix.sync.aligned.m8n8.x4.shared.b16 {%0,%1,%2,%3}, [%4];"
                 : "=r"(r[0]), "=r"(r[1]), "=r"(r[2]), "=r"(r[3]) : "r"(a));
}
__device__ __forceinline__ void mma_f16(float* d, const uint32_t* a, const uint32_t* b) {
    asm volatile(
        "mma.sync.aligned.m16n8k16.row.col.f32.f16.f16.f32 "
        "{%0,%1,%2,%3},{%4,%5,%6,%7},{%8,%9},{%0,%1,%2,%3};"
        : "+f"(d[0]), "+f"(d[1]), "+f"(d[2]), "+f"(d[3])
        : "r"(a[0]), "r"(a[1]), "r"(a[2]), "r"(a[3]), "r"(b[0]), "r"(b[1]));
}
__device__ __forceinline__ void cp16(uint32_t dst, const void* src) {
    asm volatile("cp.async.cg.shared.global [%0], [%1], 16;" ::"r"(dst), "l"(src));
}
#define CP_COMMIT() asm volatile("cp.async.commit_group;" ::: "memory")
#define CP_WAIT3() asm volatile("cp.async.wait_group 3;" ::: "memory")
#define CP_WAIT2() asm volatile("cp.async.wait_group 2;" ::: "memory")
#define CP_WAIT1() asm volatile("cp.async.wait_group 1;" ::: "memory")
#define CP_WAIT0() asm volatile("cp.async.wait_group 0;" ::: "memory")

// Newton reciprocal (no MUFU): a >= 1 here.
__device__ __forceinline__ float rcp_nr(float a) {
    float r = __uint_as_float(0x7EF311C3u - __float_as_uint(a));
    r = r * fmaf(-a, r, 2.0f);
    r = r * fmaf(-a, r, 2.0f);
    r = r * fmaf(-a, r, 2.0f);
    return r;
}
__device__ __forceinline__ float nexp(float x) {  // exp(-clamp(x, +/-40))
    x = fminf(fmaxf(x, -40.f), 40.f);
    return expf(-x);
}
__device__ __forceinline__ uint32_t packh2(float f0, float f1) {
    __half h0 = __float2half(f0), h1 = __float2half(f1);
    return (uint32_t)__half_as_ushort(h0) | ((uint32_t)__half_as_ushort(h1) << 16);
}

// ---------------------------------------------------------------------------
// Kernel 1: projections -> exp tables; arg1 -> fp16 single; arg2 -> fp16 hi/lo.
// ---------------------------------------------------------------------------
__global__ __launch_bounds__(256) void proj_convert(
    const float* __restrict__ arg1, const float* __restrict__ arg2,
    const float* __restrict__ Wg, const float* __restrict__ V,
    const float* __restrict__ Bg) {
    extern __shared__ float wsm[];  // [0:8192) Wg^T [s][1024], [8192:16384) V^T
    for (int t = threadIdx.x; t < 8192; t += 256) {
        int d = t >> 3, s = t & 7;
        wsm[s * 1024 + d] = Wg[t];
        wsm[8192 + s * 1024 + d] = V[t];
    }
    __syncthreads();
    int w = threadIdx.x >> 5, lane = threadIdx.x & 31;
    int r = blockIdx.x * 8 + w;
    const float* a1 = arg1 + (size_t)r * D_;
    const float* a2 = arg2 + (size_t)r * D_;
    float aG1[8] = {}, aG2[8] = {}, aS1[8] = {}, aS2[8] = {};
#pragma unroll
    for (int t = 0; t < 16; t++) {
        int d = lane + t * 32;
        float v1 = a1[d], v2 = a2[d];
        g_A1h[(size_t)r * D_ + d] = __float2half(v1);
        __half h2 = __float2half(v2);
        g_A2h[(size_t)r * D_ + d] = h2;
        g_A2l[(size_t)r * D_ + d] = __float2half(v2 - __half2float(h2));
#pragma unroll
        for (int s = 0; s < 8; s++) {
            aG1[s] += v1 * wsm[s * 1024 + d];
            aG2[s] += v2 * wsm[s * 1024 + 512 + d];
            aS1[s] += v1 * wsm[8192 + s * 1024 + d];
            aS2[s] += v2 * wsm[8192 + s * 1024 + 512 + d];
        }
    }
#pragma unroll
    for (int m = 16; m; m >>= 1) {
#pragma unroll
        for (int s = 0; s < 8; s++) {
            aG1[s] += __shfl_xor_sync(0xffffffffu, aG1[s], m);
            aG2[s] += __shfl_xor_sync(0xffffffffu, aG2[s], m);
            aS1[s] += __shfl_xor_sync(0xffffffffu, aS1[s], m);
            aS2[s] += __shfl_xor_sync(0xffffffffu, aS2[s], m);
        }
    }
    if (lane == 0) {
#pragma unroll
        for (int s = 0; s < 8; s++) {
            g_EG1[r * 8 + s] = nexp(aG1[s]);
            g_EG2[r * 8 + s] = nexp(aG2[s] + Bg[s]);
            g_ES1[r * 8 + s] = nexp(aS1[s]);
            g_ES2[r * 8 + s] = nexp(aS2[s]);
        }
    }
}

// ---------------------------------------------------------------------------
// Kernel 2: Mr [k,d,e] -> transposed fp16 hi/lo Mt [k,e,d].
// ---------------------------------------------------------------------------
__global__ void mr_transpose(const float* __restrict__ Mr) {
    __shared__ float tile[32][33];
    int k = blockIdx.z;
    int d0 = blockIdx.y * 32, e0 = blockIdx.x * 32;
    const float* src = Mr + (size_t)k * D_ * D_;
    for (int rr = threadIdx.y; rr < 32; rr += 8)
        tile[rr][threadIdx.x] = src[(size_t)(d0 + rr) * D_ + e0 + threadIdx.x];
    __syncthreads();
    __half* dh = g_Mth + (size_t)k * D_ * D_;
    __half* dl = g_Mtl + (size_t)k * D_ * D_;
    for (int rr = threadIdx.y; rr < 32; rr += 8) {
        float v = tile[threadIdx.x][rr];
        __half h = __float2half(v);
        dh[(size_t)(e0 + rr) * D_ + d0 + threadIdx.x] = h;
        dl[(size_t)(e0 + rr) * D_ + d0 + threadIdx.x] =
            __float2half(v - __half2float(h));
    }
}

// ---------------------------------------------------------------------------
// Kernel 3: P = arg1 @ Mr^T, fp16 2-pass: P = A1h·(Mh + Ml). CTA 128x128,
// BK=32, 512 threads, 16 warps 4Mx4N. 4-stage cp.async pipeline.
// stage: Ah@0 | Bh@10240 | Bl@20480 = 30720. grid = (4, 128, 8).
// ---------------------------------------------------------------------------
#define STG_P 30720u
__global__ __launch_bounds__(512, 1) void pmul_mma() {
    const int k = blockIdx.z, mB = blockIdx.y, nB = blockIdx.x;
    extern __shared__ char sm[];
    const uint32_t sb = smem_u32(sm);
    const int tid = threadIdx.x, wid = tid >> 5, lane = tid & 31;
    const int warpM = wid >> 2, warpN = wid & 3;

    const __half* pAh = g_A1h + (size_t)mB * 128 * D_;
    const __half* pBh = g_Mth + ((size_t)k * D_ + nB * 128) * D_;
    const __half* pBl = g_Mtl + ((size_t)k * D_ + nB * 128) * D_;

    auto load_chunk = [&](int c, int buf) {
        uint32_t dstb = sb + (uint32_t)buf * STG_P;
#pragma unroll
        for (int rr = 0; rr < 3; rr++) {
            int op = tid + rr * 512;
            int tile = op >> 9;               // 0 Ah 1 Bh 2 Bl
            int row = (op >> 2) & 127;
            int seg = op & 3;
            const __half* g = (tile == 0) ? pAh : (tile == 1) ? pBh : pBl;
            uint32_t off = (uint32_t)tile * 10240u + (uint32_t)(row * 80 + seg * 16);
            cp16(dstb + off, g + (size_t)row * D_ + c * 32 + seg * 8);
        }
    };

    float acc[2][4][4];
#pragma unroll
    for (int mt = 0; mt < 2; mt++)
#pragma unroll
        for (int nt = 0; nt < 4; nt++)
#pragma unroll
            for (int q = 0; q < 4; q++) acc[mt][nt][q] = 0.f;

    load_chunk(0, 0); CP_COMMIT();
    load_chunk(1, 1); CP_COMMIT();
    load_chunk(2, 2); CP_COMMIT();
    const int lm = lane & 15, lk = lane >> 4;
    const int bp_row = ((lane >> 4) & 1) * 8 + (lane & 7);
    const int bp_k = (lane >> 3) & 1;

    for (int c = 0; c < 16; c++) {
        int buf = c & 3;
        if (c + 3 < 16) { load_chunk(c + 3, (c + 3) & 3); CP_COMMIT(); CP_WAIT3(); }
        else if (c + 2 < 16) CP_WAIT2();
        else if (c + 1 < 16) CP_WAIT1();
        else CP_WAIT0();
        __syncthreads();
        uint32_t sbuf = sb + (uint32_t)buf * STG_P;
#pragma unroll
        for (int ks = 0; ks < 2; ks++) {
            uint32_t ah[2][4], bh[4][2], bl[4][2];
#pragma unroll
            for (int mt = 0; mt < 2; mt++) {
                uint32_t a = sbuf + (uint32_t)((warpM * 32 + mt * 16 + lm) * 80 +
                                               (ks * 16 + lk * 8) * 2);
                ldm_x4(ah[mt], a);
            }
#pragma unroll
            for (int p = 0; p < 2; p++) {
                uint32_t a = sbuf + 10240u +
                             (uint32_t)((warpN * 32 + p * 16 + bp_row) * 80 +
                                        (ks * 16 + bp_k * 8) * 2);
                uint32_t t4[4];
                ldm_x4(t4, a);
                bh[2 * p][0] = t4[0]; bh[2 * p][1] = t4[1];
                bh[2 * p + 1][0] = t4[2]; bh[2 * p + 1][1] = t4[3];
                ldm_x4(t4, a + 10240u);
                bl[2 * p][0] = t4[0]; bl[2 * p][1] = t4[1];
                bl[2 * p + 1][0] = t4[2]; bl[2 * p + 1][1] = t4[3];
            }
            // pass-ordered: 8 independent accs between same-acc reuse
#pragma unroll
            for (int mt = 0; mt < 2; mt++)
#pragma unroll
                for (int nt = 0; nt < 4; nt++) mma_f16(acc[mt][nt], ah[mt], bh[nt]);
#pragma unroll
            for (int mt = 0; mt < 2; mt++)
#pragma unroll
                for (int nt = 0; nt < 4; nt++) mma_f16(acc[mt][nt], ah[mt], bl[nt]);
        }
        __syncthreads();
    }

    // epilogue: store P as single fp16
    const int rowg0 = mB * 128 + warpM * 32;
#pragma unroll
    for (int mt = 0; mt < 2; mt++) {
#pragma unroll
        for (int half = 0; half < 2; half++) {
            int rowg = rowg0 + mt * 16 + (lane >> 2) + half * 8;
            int bb = rowg >> 9, ii = rowg & 511;
            size_t base = ((size_t)(bb * S_ + k) * L_ + ii) * D_ + nB * 128;
#pragma unroll
            for (int nt = 0; nt < 4; nt++) {
                int colg = warpN * 32 + nt * 8 + (lane & 3) * 2;
                *(uint32_t*)(g_Ph + base + colg) =
                    packh2(acc[mt][nt][half * 2], acc[mt][nt][half * 2 + 1]);
            }
        }
    }
}

// ---------------------------------------------------------------------------
// Kernel 4: per (b, i-tile 128, j-tile 64): loop k, bi = Ph·(a2h + a2l)^T
// + fused factored-sigmoid gating, final sigmoid. 8 warps 4Mx2N.
// 4-stage pipeline: stage Ah@0|Bh@10240|Bl@15360 = 20480; tables @81920.
// grid = (8, 4, 32). 2 CTAs/SM.
// ---------------------------------------------------------------------------
#define STG_S 20480u
__global__ __launch_bounds__(256, 2) void score_mma(
    const float* __restrict__ U, const float* __restrict__ bvec,
    float* __restrict__ out) {
    const int b = blockIdx.z;
    const int i0 = blockIdx.y * 128;
    const int j0 = blockIdx.x * 64;
    extern __shared__ char sm[];
    const uint32_t sb = smem_u32(sm);
    float* EG1t = (float*)(sm + 81920);  // [128][9]
    float* ES1t = (float*)(sm + 86528);  // [128][9]
    float* EG2t = (float*)(sm + 91136);  // [8][64]
    float* ES2t = (float*)(sm + 93184);  // [8][64]
    const int tid = threadIdx.x, wid = tid >> 5, lane = tid & 31;
    const int warpM = wid >> 1, warpN = wid & 1;

    for (int t = tid; t < 1024; t += 256) {
        int r = t >> 3, s = t & 7;
        EG1t[r * 9 + s] = g_EG1[(size_t)(b * L_ + i0 + r) * 8 + s];
        ES1t[r * 9 + s] = g_ES1[(size_t)(b * L_ + i0 + r) * 8 + s];
    }
    for (int t = tid; t < 512; t += 256) {
        int kk = t >> 6, j = t & 63;
        EG2t[kk * 64 + j] = g_EG2[(size_t)(b * L_ + j0 + j) * 8 + kk];
        ES2t[kk * 64 + j] = g_ES2[(size_t)(b * L_ + j0 + j) * 8 + kk];
    }

    float Ur[8];
#pragma unroll
    for (int s = 0; s < 8; s++) Ur[s] = __ldg(U + s);
    float c0 = 0.f;
#pragma unroll
    for (int s = 0; s < 8; s++) c0 += Ur[s] * __ldg(bvec + s);

    const __half* pBh = g_A2h + (size_t)(b * L_ + j0) * D_;
    const __half* pBl = g_A2l + (size_t)(b * L_ + j0) * D_;

    auto load_chunk = [&](int cc, int buf) {
        int k = cc >> 4, c = cc & 15;
        const __half* pAh = g_Ph + ((size_t)(b * S_ + k) * L_ + i0) * D_;
        uint32_t dstb = sb + (uint32_t)buf * STG_S;
#pragma unroll
        for (int rr = 0; rr < 2; rr++) {
            int op = tid + rr * 256;
            int row = op >> 2, seg = op & 3;
            uint32_t off = (uint32_t)(row * 80 + seg * 16);
            cp16(dstb + off, pAh + (size_t)row * D_ + c * 32 + seg * 8);
        }
        {
            int row = tid >> 2, seg = tid & 3;
            uint32_t off = (uint32_t)(row * 80 + seg * 16);
            size_t gi = (size_t)row * D_ + c * 32 + seg * 8;
            cp16(dstb + 10240u + off, pBh + gi);
            cp16(dstb + 15360u + off, pBl + gi);
        }
    };

    float acc[2][4][4], part[2][4][4];
#pragma unroll
    for (int mt = 0; mt < 2; mt++)
#pragma unroll
        for (int nt = 0; nt < 4; nt++)
#pragma unroll
            for (int q = 0; q < 4; q++) part[mt][nt][q] = 0.f;

    load_chunk(0, 0); CP_COMMIT();
    load_chunk(1, 1); CP_COMMIT();
    load_chunk(2, 2); CP_COMMIT();
    const int lm = lane & 15, lk = lane >> 4;
    const int bp_row = ((lane >> 4) & 1) * 8 + (lane & 7);
    const int bp_k = (lane >> 3) & 1;

    for (int cc = 0; cc < 128; cc++) {
        int k = cc >> 4, c = cc & 15, buf = cc & 3;
        if (cc + 3 < 128) { load_chunk(cc + 3, (cc + 3) & 3); CP_COMMIT(); CP_WAIT3(); }
        else if (cc + 2 < 128) CP_WAIT2();
        else if (cc + 1 < 128) CP_WAIT1();
        else CP_WAIT0();
        __syncthreads();
        if (c == 0) {
#pragma unroll
            for (int mt = 0; mt < 2; mt++)
#pragma unroll
                for (int nt = 0; nt < 4; nt++)
#pragma unroll
                    for (int q = 0; q < 4; q++) acc[mt][nt][q] = 0.f;
        }
        uint32_t sbuf = sb + (uint32_t)buf * STG_S;
#pragma unroll
        for (int ks = 0; ks < 2; ks++) {
            uint32_t ah[2][4], bh[4][2], bl[4][2];
#pragma unroll
            for (int mt = 0; mt < 2; mt++) {
                uint32_t a = sbuf + (uint32_t)((warpM * 32 + mt * 16 + lm) * 80 +
                                               (ks * 16 + lk * 8) * 2);
                ldm_x4(ah[mt], a);
            }
#pragma unroll
            for (int p = 0; p < 2; p++) {
                uint32_t a = sbuf + 10240u +
                             (uint32_t)((warpN * 32 + p * 16 + bp_row) * 80 +
                                        (ks * 16 + bp_k * 8) * 2);
                uint32_t t4[4];
                ldm_x4(t4, a);
                bh[2 * p][0] = t4[0]; bh[2 * p][1] = t4[1];
                bh[2 * p + 1][0] = t4[2]; bh[2 * p + 1][1] = t4[3];
                ldm_x4(t4, a + 5120u);
                bl[2 * p][0] = t4[0]; bl[2 * p][1] = t4[1];
                bl[2 * p + 1][0] = t4[2]; bl[2 * p + 1][1] = t4[3];
            }
            // pass-ordered: 8 independent accs between same-acc reuse
#pragma unroll
            for (int mt = 0; mt < 2; mt++)
#pragma unroll
                for (int nt = 0; nt < 4; nt++) mma_f16(acc[mt][nt], ah[mt], bh[nt]);
#pragma unroll
            for (int mt = 0; mt < 2; mt++)
#pragma unroll
                for (int nt = 0; nt < 4; nt++) mma_f16(acc[mt][nt], ah[mt], bl[nt]);
        }
        if (c == 15) {
            float Uk = Ur[k];
#pragma unroll
            for (int mt = 0; mt < 2; mt++) {
                int r0 = warpM * 32 + mt * 16 + (lane >> 2);
                float eg1a = EG1t[r0 * 9 + k], es1a = ES1t[r0 * 9 + k];
                float eg1b = EG1t[(r0 + 8) * 9 + k], es1b = ES1t[(r0 + 8) * 9 + k];
#pragma unroll
                for (int nt = 0; nt < 4; nt++) {
                    int jj = warpN * 32 + nt * 8 + (lane & 3) * 2;
                    float eg2x = EG2t[k * 64 + jj], eg2y = EG2t[k * 64 + jj + 1];
                    float es2x = ES2t[k * 64 + jj], es2y = ES2t[k * 64 + jj + 1];
                    float g, s;
                    g = rcp_nr(fmaf(eg1a, eg2x, 1.f));
                    s = rcp_nr(fmaf(es1a, es2x, 1.f));
                    part[mt][nt][0] =
                        fmaf(Uk, fmaf(g, acc[mt][nt][0] - s, s), part[mt][nt][0]);
                    g = rcp_nr(fmaf(eg1a, eg2y, 1.f));
                    s = rcp_nr(fmaf(es1a, es2y, 1.f));
                    part[mt][nt][1] =
                        fmaf(Uk, fmaf(g, acc[mt][nt][1] - s, s), part[mt][nt][1]);
                    g = rcp_nr(fmaf(eg1b, eg2x, 1.f));
                    s = rcp_nr(fmaf(es1b, es2x, 1.f));
                    part[mt][nt][2] =
                        fmaf(Uk, fmaf(g, acc[mt][nt][2] - s, s), part[mt][nt][2]);
                    g = rcp_nr(fmaf(eg1b, eg2y, 1.f));
                    s = rcp_nr(fmaf(es1b, es2y, 1.f));
                    part[mt][nt][3] =
                        fmaf(Uk, fmaf(g, acc[mt][nt][3] - s, s), part[mt][nt][3]);
                }
            }
        }
        __syncthreads();
    }

    // final sigmoid + store
#pragma unroll
    for (int mt = 0; mt < 2; mt++) {
        int ibase = i0 + warpM * 32 + mt * 16 + (lane >> 2);
#pragma unroll
        for (int half = 0; half < 2; half++) {
            float* orow = out + ((size_t)b * L_ + ibase + half * 8) * L_ + j0;
#pragma unroll
            for (int nt = 0; nt < 4; nt++) {
                int jj = warpN * 32 + nt * 8 + (lane & 3) * 2;
                float z0 = part[mt][nt][half * 2 + 0] + c0;
                float z1 = part[mt][nt][half * 2 + 1] + c0;
                float2 v;
                v.x = rcp_nr(1.f + __expf(-z0));
                v.y = rcp_nr(1.f + __expf(-z1));
                *(float2*)(orow + jj) = v;
            }
        }
    }
}

// ---------------------------------------------------------------------------
extern "C" void kernel_launch(void* const* d_in, const int* in_sizes, int n_in,
                              void* d_out, int out_size) {
    const float* arg1 = (const float*)d_in[0];
    const float* arg2 = (const float*)d_in[1];
    const float* Wg   = (const float*)d_in[2];
    const float* Bg   = (const float*)d_in[3];
    const float* Mr   = (const float*)d_in[4];
    const float* V    = (const float*)d_in[5];
    const float* bvec = (const float*)d_in[6];
    const float* U    = (const float*)d_in[7];
    float* out = (float*)d_out;
    (void)in_sizes; (void)n_in; (void)out_size;

    const int SMEM_PROJ = 65536;
    const int SMEM_B = 4 * 30720;            // 122880
    const int SMEM_C = 4 * 20480 + 13312;    // 95232
    cudaFuncSetAttribute(proj_convert, cudaFuncAttributeMaxDynamicSharedMemorySize, SMEM_PROJ);
    cudaFuncSetAttribute(pmul_mma, cudaFuncAttributeMaxDynamicSharedMemorySize, SMEM_B);
    cudaFuncSetAttribute(score_mma, cudaFuncAttributeMaxDynamicSharedMemorySize, SMEM_C);

    proj_convert<<<BL_ / 8, 256, SMEM_PROJ>>>(arg1, arg2, Wg, V, Bg);
    mr_transpose<<<dim3(16, 16, 8), dim3(32, 8)>>>(Mr);
    pmul_mma<<<dim3(4, 128, 8), 512, SMEM_B>>>();
    score_mma<<<dim3(8, 4, 32), 256, SMEM_C>>>(U, bvec, out);
}